// round 2
// baseline (speedup 1.0000x reference)
#include <cuda_runtime.h>
#include <cuda_bf16.h>
#include <math.h>

#define TT  512
#define BB  64
#define DIN 256
#define NN  1024
#define OO  128

// ---------------- device scratch (no cudaMalloc allowed) ----------------
__device__ float    g_xw[(TT - 1) * NN * BB];   // [t][n][b], t = 0..510 feeds step t+1
__device__ float    g_sbuf[2 * NN * BB];        // ping-pong state, transposed [n][b]
__device__ float    g_part[64 * 64 * 16];       // per-ntile k-half-0 partials (thread-mapped)
__device__ unsigned g_bar;                      // global barrier arrival counter
__device__ unsigned g_release;                  // last released step (monotonic per launch)
__device__ unsigned g_pflag[64];                // per-ntile partial-ready step flag

// ---------------- acquire/release helpers ----------------
__device__ __forceinline__ unsigned ld_acq(const unsigned* p) {
    unsigned v;
    asm volatile("ld.acquire.gpu.u32 %0, [%1];" : "=r"(v) : "l"(p));
    return v;
}
__device__ __forceinline__ void st_rel(unsigned* p, unsigned v) {
    asm volatile("st.release.gpu.u32 [%0], %1;" :: "l"(p), "r"(v) : "memory");
}

// ---------------- init: reset sync state, zero s[:,0,:] ----------------
__global__ void init_kernel(float* __restrict__ sout) {
    int idx = blockIdx.x * blockDim.x + threadIdx.x;
    if (idx == 0) { g_bar = 0; g_release = 0; }
    if (idx < 64) g_pflag[idx] = 0;
    if (idx < NN * BB) {
        g_sbuf[idx] = 0.0f;                       // phase-0 state = 0
        int b = idx / NN, n = idx % NN;
        sout[((size_t)b * TT + 0) * NN + n] = 0.0f;  // s[:,0,:] = 0
    }
}

// ---------------- XW = X[:,t,:] @ Win, stored [t][n][b] ----------------
// grid (511, 16), block 256. tile 64(b) x 64(n), K=256 in chunks of 16.
__global__ void xw_kernel(const float* __restrict__ X, const float* __restrict__ Win) {
    const int t  = blockIdx.x;          // 0..510
    const int c0 = blockIdx.y * 64;
    __shared__ float xs[16][BB];        // [d][b]
    __shared__ float ws[16][64];        // [d][c]
    const int tid = threadIdx.x;
    const int r0 = (tid & 15) * 4;      // b rows
    const int cc = (tid >> 4) * 4;      // local cols
    float acc[4][4] = {};

    for (int d0 = 0; d0 < DIN; d0 += 16) {
        {
            int b  = tid & 63;
            int d4 = (tid >> 6) * 4;    // 0,4,8,12
            float4 xv = *(const float4*)&X[((size_t)b * TT + t) * DIN + d0 + d4];
            xs[d4 + 0][b] = xv.x; xs[d4 + 1][b] = xv.y;
            xs[d4 + 2][b] = xv.z; xs[d4 + 3][b] = xv.w;
        }
        {
            int dr = tid >> 4;          // 0..15
            int c4 = (tid & 15) * 4;
            *(float4*)&ws[dr][c4] = *(const float4*)&Win[(size_t)(d0 + dr) * NN + c0 + c4];
        }
        __syncthreads();
        #pragma unroll
        for (int d = 0; d < 16; d++) {
            float4 a = *(const float4*)&xs[d][r0];
            float4 w = *(const float4*)&ws[d][cc];
            acc[0][0] += a.x * w.x; acc[0][1] += a.x * w.y; acc[0][2] += a.x * w.z; acc[0][3] += a.x * w.w;
            acc[1][0] += a.y * w.x; acc[1][1] += a.y * w.y; acc[1][2] += a.y * w.z; acc[1][3] += a.y * w.w;
            acc[2][0] += a.z * w.x; acc[2][1] += a.z * w.y; acc[2][2] += a.z * w.z; acc[2][3] += a.z * w.w;
            acc[3][0] += a.w * w.x; acc[3][1] += a.w * w.y; acc[3][2] += a.w * w.z; acc[3][3] += a.w * w.w;
        }
        __syncthreads();
    }
    #pragma unroll
    for (int j = 0; j < 4; j++) {
        float4 v = make_float4(acc[0][j], acc[1][j], acc[2][j], acc[3][j]);
        *(float4*)&g_xw[((size_t)t * NN + c0 + cc + j) * BB + r0] = v;
    }
}

// ---------------- persistent recurrence kernel ----------------
// 128 blocks x 128 threads. block = (ntile 0..63, khalf 0..1).
// Each block: acc[64x16] over its K half; khalf1 finalizes tanh.
__global__ void __launch_bounds__(128, 1) rnn_kernel(const float* __restrict__ W,
                                                     float* __restrict__ sout) {
    const int bx    = blockIdx.x;
    const int ntile = bx >> 1;
    const int kh    = bx & 1;
    const int c0    = ntile * 16;
    const int kbase = kh * 512;
    const int tid   = threadIdx.x;
    const int r0    = (tid & 15) * 4;   // b rows (4)
    const int cc    = (tid >> 4) * 2;   // local cols (2)

    __shared__ float ssm[2][32][BB];    // [buf][k][b]
    __shared__ float wsm[2][32][16];    // [buf][k][c]

    const int wk = tid >> 2;            // W loader row 0..31
    const int wc = (tid & 3) * 4;       // W loader col group

    for (int t = 1; t < TT; t++) {
        const float* __restrict__ sprev = &g_sbuf[((t - 1) & 1) * (NN * BB)];
        float acc[4][2] = {};

        // prologue: chunk 0 into buf 0
        {
            const float4* sv = (const float4*)(sprev + (size_t)kbase * BB);
            float4* d = (float4*)&ssm[0][0][0];
            #pragma unroll
            for (int i = 0; i < 4; i++) d[tid + 128 * i] = sv[tid + 128 * i];
            *(float4*)&wsm[0][wk][wc] = *(const float4*)&W[(size_t)(kbase + wk) * NN + c0 + wc];
        }
        __syncthreads();

        for (int kc = 0; kc < 16; kc++) {
            const int buf = kc & 1;
            float4 pfs[4]; float4 pfw;
            if (kc < 15) {
                const float4* sv = (const float4*)(sprev + (size_t)(kbase + (kc + 1) * 32) * BB);
                #pragma unroll
                for (int i = 0; i < 4; i++) pfs[i] = sv[tid + 128 * i];
                pfw = *(const float4*)&W[(size_t)(kbase + (kc + 1) * 32 + wk) * NN + c0 + wc];
            }
            const float (*sb)[BB] = ssm[buf];
            const float (*wb)[16] = wsm[buf];
            #pragma unroll
            for (int k = 0; k < 32; k++) {
                float4 sv = *(const float4*)&sb[k][r0];
                float2 wv = *(const float2*)&wb[k][cc];
                acc[0][0] += sv.x * wv.x; acc[0][1] += sv.x * wv.y;
                acc[1][0] += sv.y * wv.x; acc[1][1] += sv.y * wv.y;
                acc[2][0] += sv.z * wv.x; acc[2][1] += sv.z * wv.y;
                acc[3][0] += sv.w * wv.x; acc[3][1] += sv.w * wv.y;
            }
            if (kc < 15) {
                float4* d = (float4*)&ssm[buf ^ 1][0][0];
                #pragma unroll
                for (int i = 0; i < 4; i++) d[tid + 128 * i] = pfs[i];
                *(float4*)&wsm[buf ^ 1][wk][wc] = pfw;
                __syncthreads();
            }
        }

        float* p = &g_part[(size_t)ntile * 1024 + tid * 8];
        if (kh == 0) {
            // publish partials, raise per-tile flag
            *(float4*)&p[0] = make_float4(acc[0][0], acc[1][0], acc[2][0], acc[3][0]);
            *(float4*)&p[4] = make_float4(acc[0][1], acc[1][1], acc[2][1], acc[3][1]);
            __threadfence();
            __syncthreads();
            if (tid == 0) st_rel(&g_pflag[ntile], (unsigned)t);
        } else {
            // wait for partner partials
            if (tid == 0) { while (ld_acq(&g_pflag[ntile]) < (unsigned)t) {} }
            __syncthreads();
            float4 p0 = *(const float4*)&p[0];
            float4 p1 = *(const float4*)&p[4];
            const float* xwp = &g_xw[((size_t)(t - 1) * NN + c0 + cc) * BB];
            float4 x0 = *(const float4*)&xwp[0 * BB + r0];
            float4 x1 = *(const float4*)&xwp[1 * BB + r0];
            float sn[4][2];
            sn[0][0] = tanhf(acc[0][0] + p0.x + x0.x);
            sn[1][0] = tanhf(acc[1][0] + p0.y + x0.y);
            sn[2][0] = tanhf(acc[2][0] + p0.z + x0.z);
            sn[3][0] = tanhf(acc[3][0] + p0.w + x0.w);
            sn[0][1] = tanhf(acc[0][1] + p1.x + x1.x);
            sn[1][1] = tanhf(acc[1][1] + p1.y + x1.y);
            sn[2][1] = tanhf(acc[2][1] + p1.z + x1.z);
            sn[3][1] = tanhf(acc[3][1] + p1.w + x1.w);
            // state buffer (transposed [n][b])
            float* sb = &g_sbuf[(t & 1) * (NN * BB)];
            *(float4*)&sb[(size_t)(c0 + cc + 0) * BB + r0] =
                make_float4(sn[0][0], sn[1][0], sn[2][0], sn[3][0]);
            *(float4*)&sb[(size_t)(c0 + cc + 1) * BB + r0] =
                make_float4(sn[0][1], sn[1][1], sn[2][1], sn[3][1]);
            // output s[b][t][n]
            #pragma unroll
            for (int i = 0; i < 4; i++) {
                float2 v = make_float2(sn[i][0], sn[i][1]);
                *(float2*)&sout[((size_t)(r0 + i) * TT + t) * NN + c0 + cc] = v;
            }
            __threadfence();
            __syncthreads();
        }

        // global step barrier (monotonic)
        if (tid == 0) {
            unsigned v = atomicAdd(&g_bar, 1u) + 1u;
            if (v == (unsigned)(128 * t)) {
                __threadfence();
                st_rel(&g_release, (unsigned)t);
            } else {
                while (ld_acq(&g_release) < (unsigned)t) {}
            }
        }
        __syncthreads();
    }
}

// ---------------- out = s @ Wout + bout ----------------
// grid (512, 2), block 256. tile 64(m=b*T+t) x 64(o), K=1024 chunks of 16.
__global__ void out_kernel(const float* __restrict__ s, const float* __restrict__ Wout,
                           const float* __restrict__ bout, float* __restrict__ out) {
    const int m0 = blockIdx.x * 64;
    const int c0 = blockIdx.y * 64;
    __shared__ float as[16][64];        // [k][m]
    __shared__ float ws[16][64];        // [k][o]
    const int tid = threadIdx.x;
    const int r0 = (tid & 15) * 4;
    const int cc = (tid >> 4) * 4;
    float acc[4][4] = {};

    for (int k0 = 0; k0 < NN; k0 += 16) {
        {
            int m  = tid & 63;
            int k4 = (tid >> 6) * 4;
            float4 v = *(const float4*)&s[(size_t)(m0 + m) * NN + k0 + k4];
            as[k4 + 0][m] = v.x; as[k4 + 1][m] = v.y;
            as[k4 + 2][m] = v.z; as[k4 + 3][m] = v.w;
        }
        {
            int kr = tid >> 4;
            int c4 = (tid & 15) * 4;
            *(float4*)&ws[kr][c4] = *(const float4*)&Wout[(size_t)(k0 + kr) * OO + c0 + c4];
        }
        __syncthreads();
        #pragma unroll
        for (int k = 0; k < 16; k++) {
            float4 a = *(const float4*)&as[k][r0];
            float4 w = *(const float4*)&ws[k][cc];
            acc[0][0] += a.x * w.x; acc[0][1] += a.x * w.y; acc[0][2] += a.x * w.z; acc[0][3] += a.x * w.w;
            acc[1][0] += a.y * w.x; acc[1][1] += a.y * w.y; acc[1][2] += a.y * w.z; acc[1][3] += a.y * w.w;
            acc[2][0] += a.z * w.x; acc[2][1] += a.z * w.y; acc[2][2] += a.z * w.z; acc[2][3] += a.z * w.w;
            acc[3][0] += a.w * w.x; acc[3][1] += a.w * w.y; acc[3][2] += a.w * w.z; acc[3][3] += a.w * w.w;
        }
        __syncthreads();
    }
    float4 bv = *(const float4*)&bout[c0 + cc];
    #pragma unroll
    for (int i = 0; i < 4; i++) {
        float4 v = make_float4(acc[i][0] + bv.x, acc[i][1] + bv.y,
                               acc[i][2] + bv.z, acc[i][3] + bv.w);
        *(float4*)&out[(size_t)(m0 + r0 + i) * OO + c0 + cc] = v;
    }
}

// ---------------- launch ----------------
extern "C" void kernel_launch(void* const* d_in, const int* in_sizes, int n_in,
                              void* d_out, int out_size) {
    const float* X    = (const float*)d_in[0];  // [B,T,DIN]
    const float* Win  = (const float*)d_in[1];  // [DIN,N]
    const float* W    = (const float*)d_in[2];  // [N,N]
    const float* Wout = (const float*)d_in[3];  // [N,O]
    const float* bout = (const float*)d_in[4];  // [O]

    float* s_out = (float*)d_out;                            // [B,T,N]
    float* o_out = (float*)d_out + (size_t)BB * TT * NN;     // [B,T,O]

    init_kernel<<<256, 256>>>(s_out);
    xw_kernel<<<dim3(TT - 1, 16), 256>>>(X, Win);
    rnn_kernel<<<128, 128>>>(W, s_out);
    out_kernel<<<dim3((BB * TT) / 64, OO / 64), 256>>>(s_out, Wout, bout, o_out);
}